// round 16
// baseline (speedup 1.0000x reference)
#include <cuda_runtime.h>
#include <cstdint>
#include <math.h>

#define NMAXA 8192
#define PMAXP 131072

typedef unsigned long long ull;

// ---------------- device scratch ----------------
__device__ float g_cgw[4096];                      // dense CG [aF][bF*16+MF]
__device__ float g_sym0[136 * 16];
__device__ float g_sym1[45 * 16];
__device__ float g_sym2[10 * 4];
__device__ float g_c000[1];
__device__ float g_emb[NMAXA * 32];
__device__ float g_feats[(size_t)NMAXA * 1920];
__device__ float g_feats2[(size_t)NMAXA * 1920];
__device__ float g_S[NMAXA * 240];
__device__ float g_W[(size_t)PMAXP * 256];         // per-pair W (sorted order)
__device__ int   g_snbr[PMAXP];
__device__ int   g_counts[NMAXA];
__device__ int   g_starts[NMAXA];
__device__ int   g_cursor[NMAXA];
__device__ int   g_sorted[PMAXP];
__device__ int   g_ctr;

struct CGBuf { float v[3436]; };

__device__ __forceinline__ int shoff(int l) { return l==0?0:l==1?1:l==2?4:9; }

__device__ constexpr int OFFS[16] = {0,256,448,640,832,960,1088,1216,1344,
                                     1472,1536,1600,1664,1728,1792,1856};

__constant__ int c_e_l1[34]={0,0,0,0, 1,1,1,1,1,1,1,1,1, 2,2,2,2,2,2,2,2,2,2,2, 3,3,3,3,3,3,3,3,3,3};
__constant__ int c_e_l2[34]={0,1,2,3, 0,1,1,1,2,2,2,3,3, 0,1,1,1,2,2,2,2,3,3,3, 0,1,1,2,2,2,3,3,3,3};
__constant__ int c_e_L [34]={0,1,2,3, 1,0,1,2,1,2,3,2,3, 2,1,2,3,0,1,2,3,1,2,3, 3,2,3,1,2,3,0,1,2,3};
__constant__ int c_e_off[34]={0,1,10,35, 84,93,102,129,174,219,294,399,504,
                              651,676,721,796,901,926,1001,1126,1301,1406,1581,
                              1826,1875,1980,2127,2232,2407,2652,2701,2848,3093};

#define FMA2(ACC,PD,CV) asm("fma.rn.f32x2 %0, %1, %2, %0;" : "+l"(ACC) : "l"(PD), "l"(CV))
#define MUL2(OUT,A,B)   asm("mul.rn.f32x2 %0, %1, %2;" : "=l"(OUT) : "l"(A), "l"(B))
#define ADD2(ACC,V)     asm("add.rn.f32x2 %0, %0, %1;" : "+l"(ACC) : "l"(V))
#define PACK2(PD,P)     asm("mov.b64 %0, {%1, %1};" : "=l"(PD) : "f"(P))
#define UNPK2(LO,HI,PD) asm("mov.b64 {%0, %1}, %2;" : "=f"(LO), "=f"(HI) : "l"(PD))

// ---------------- CG build ----------------
__global__ void k_initcg(CGBuf cg) {
    int t = threadIdx.x;
    for (int i = t; i < 4096; i += 256) g_cgw[i] = 0.f;
    __syncthreads();
    for (int e = 0; e < 34; e++) {
        int l1 = c_e_l1[e], l2 = c_e_l2[e], L = c_e_L[e];
        int d2 = 2*l2+1, dL = 2*L+1;
        int sz = (2*l1+1)*d2*dL, off = c_e_off[e];
        for (int i = t; i < sz; i += 256) {
            int M = i % dL; int r = i / dL; int b = r % d2; int a = r / d2;
            g_cgw[(shoff(l1)+a)*256 + (shoff(l2)+b)*16 + shoff(L)+M] = cg.v[off + i];
        }
        __syncthreads();
    }
    for (int i = t; i < 136*16; i += 256) {
        int pi = i >> 4, M = i & 15;
        int a = 0, base = 0;
        while (base + (16 - a) <= pi) { base += 16 - a; a++; }
        int b = a + (pi - base);
        float v = g_cgw[a*256 + b*16 + M];
        if (a != b) v += g_cgw[b*256 + a*16 + M];
        g_sym0[i] = v;
    }
    for (int i = t; i < 45*16; i += 256) {
        int pi = i >> 4, M = i & 15;
        int a = 0, base = 0;
        while (base + (9 - a) <= pi) { base += 9 - a; a++; }
        int b = a + (pi - base);
        float v = 0.f;
        if (M < 9) {
            v = g_cgw[a*256 + b*16 + M];
            if (a != b) v += g_cgw[b*256 + a*16 + M];
        }
        g_sym1[i] = v;
    }
    for (int i = t; i < 40; i += 256) {
        int pi = i >> 2, M = i & 3;
        int a = 0, base = 0;
        while (base + (4 - a) <= pi) { base += 4 - a; a++; }
        int b = a + (pi - base);
        float v = g_cgw[a*256 + b*16 + M];
        if (a != b) v += g_cgw[b*256 + a*16 + M];
        g_sym2[i] = v;
    }
    if (t == 0) g_c000[0] = g_cgw[0];
}

// ---------------- embeddings, counting sort ----------------
__global__ void k_misc1(const float* __restrict__ tab, const int* __restrict__ spec, int N) {
    int i = blockIdx.x * blockDim.x + threadIdx.x;
    if (i == 0) g_ctr = 0;
    if (i < N * 32) g_emb[i] = tab[spec[i >> 5] * 32 + (i & 31)];
    if (i < N) g_counts[i] = 0;
    if (i < N * 240) g_S[i] = 0.f;
}

__global__ void k_hist(const int* __restrict__ centers, int P) {
    int p = blockIdx.x * blockDim.x + threadIdx.x;
    if (p < P) atomicAdd(&g_counts[centers[p]], 1);
}

__global__ void __launch_bounds__(1024) k_scan(int N) {
    __shared__ int wsum[32];
    int t = threadIdx.x;
    int lane = t & 31, wid = t >> 5;
    int base = t * 8;
    int v[8]; int s = 0;
    #pragma unroll
    for (int j = 0; j < 8; j++) {
        v[j] = (base + j < N) ? g_counts[base + j] : 0;
        s += v[j];
    }
    int ps = s;
    #pragma unroll
    for (int o = 1; o < 32; o <<= 1) {
        int u = __shfl_up_sync(0xffffffffu, ps, o);
        if (lane >= o) ps += u;
    }
    if (lane == 31) wsum[wid] = ps;
    __syncthreads();
    if (wid == 0) {
        int w = wsum[lane];
        int pw = w;
        #pragma unroll
        for (int o = 1; o < 32; o <<= 1) {
            int u = __shfl_up_sync(0xffffffffu, pw, o);
            if (lane >= o) pw += u;
        }
        wsum[lane] = pw - w;
    }
    __syncthreads();
    int ex = wsum[wid] + ps - s;
    #pragma unroll
    for (int j = 0; j < 8; j++) {
        if (base + j < N) { g_starts[base + j] = ex; g_cursor[base + j] = ex; }
        ex += v[j];
    }
}

__global__ void k_scatter(const int* __restrict__ centers, int P) {
    int p = blockIdx.x * blockDim.x + threadIdx.x;
    if (p < P) { int pos = atomicAdd(&g_cursor[centers[p]], 1); g_sorted[pos] = p; }
}

// ---------------- per-pair W precompute, 8 pairs per block ----------------
__global__ void __launch_bounds__(256) k_Wb(const float* __restrict__ sh,
                                            const float* __restrict__ rb,
                                            const int* __restrict__ neighbors, int P) {
    __shared__ float sEp[16][8];
    int t = threadIdx.x;
    int pos0 = blockIdx.x * 8;
    if (t < 128) {
        int pb = t >> 4, a = t & 15;
        int pos = pos0 + pb;
        float e = 0.f;
        if (pos < P) {
            int p = g_sorted[pos];
            if (a == 0) g_snbr[pos] = neighbors[p];
            int l   = (a==0)?0:(a<4)?1:(a<9)?2:3;
            int nrl = (l==0?8:l==1?6:l==2?4:2);
            int rbo = (l==0?0:l==1?8:l==2?14:18);
            float s = 0.f;
            for (int r = 0; r < nrl; r++) s += rb[p*20 + rbo + r];
            e = sh[p*16 + a] * 0.1f * s;
        }
        sEp[a][pb] = e;
    }
    ull cA[16];
    #pragma unroll
    for (int a = 0; a < 16; a++) { float c = g_cgw[a*256 + t]; PACK2(cA[a], c); }
    __syncthreads();
    #pragma unroll
    for (int i = 0; i < 4; i++) {
        ull acc = 0ull;
        #pragma unroll
        for (int a = 0; a < 16; a++) {
            ull e2 = *(const ull*)(&sEp[a][2*i]);
            FMA2(acc, e2, cA[a]);
        }
        float v0, v1; UNPK2(v0, v1, acc);
        int pos = pos0 + 2*i;
        if (pos < P)     g_W[(size_t)pos*256 + t]     = v0;
        if (pos + 1 < P) g_W[(size_t)(pos+1)*256 + t] = v1;
    }
}

// ---------------- invariant MP ----------------
__global__ void k_invA(const float* __restrict__ sh, const float* __restrict__ rb,
                       const int* __restrict__ centers, const int* __restrict__ neighbors,
                       const int* __restrict__ spec, int P) {
    int idx = blockIdx.x * blockDim.x + threadIdx.x;
    int p = idx >> 6, j = idx & 63;
    if (p >= P || j >= 60) return;
    int l, m, nr;
    if (j < 8)       { l = 0; m = 0;        nr = j; }
    else if (j < 26) { l = 1; int r = j-8;  m = r/6; nr = r%6; }
    else if (j < 46) { l = 2; int r = j-26; m = r/4; nr = r%4; }
    else             { l = 3; int r = j-46; m = r/2; nr = r%2; }
    int shf = shoff(l) + m;
    int rbf = (l==0?0:l==1?8:l==2?14:18) + nr;
    float val = sh[p*16 + shf] * 0.1f * rb[p*20 + rbf];
    int s = spec[neighbors[p]];
    atomicAdd(&g_S[(centers[p]*4 + s)*60 + j], val);
}

__global__ void __launch_bounds__(256) k_invB(const float* __restrict__ tab, int N) {
    int n = blockIdx.x, t = threadIdx.x;
    #pragma unroll
    for (int j = 0; j < 8; j++) {
        int f = j*256 + t;
        if (f >= 1920) break;
        int l, m, k;
        if (f < 256)       { l = 0; m = 0;         k = f; }
        else if (f < 832)  { int r = f-256; l = 1; m = r/192; k = r - m*192; }
        else if (f < 1472) { int r = f-832; l = 2; m = r>>7;  k = r & 127; }
        else               { int r = f-1472;l = 3; m = r>>6;  k = r & 63; }
        int nr = k >> 5, c = k & 31;
        int nrl = (l==0?8:l==1?6:l==2?4:2);
        int jb  = (l==0?0:l==1?8:l==2?26:46);
        int jj = jb + m*nrl + nr;
        const float* Sp = &g_S[n*240 + jj];
        float s = 0.f;
        #pragma unroll
        for (int sp = 0; sp < 4; sp++) s += Sp[sp*60] * tab[sp*32 + c];
        g_feats[(size_t)n*1920 + f] = 0.1f * s;
    }
}

// ---------------- unified tensor product (layer 1) ----------------
__global__ void __launch_bounds__(256) k_tpA(int N) {
    __shared__ float sC0[136 * 16];
    __shared__ float sC1[45 * 16];
    __shared__ float sC2[44];
    int t = threadIdx.x;
    for (int i = t; i < 2176; i += 256) sC0[i] = g_sym0[i];
    for (int i = t; i < 720; i += 256) sC1[i] = g_sym1[i];
    if (t < 40) sC2[t] = g_sym2[t];
    if (t == 40) sC2[40] = g_c000[0];
    __syncthreads();
    int atom = blockIdx.x * 4 + (t >> 6);
    if (atom >= N) return;
    int k = t & 63;
    float* rowb = g_feats + (size_t)atom * 1920;

    {
        float* row = rowb + k;
        float A[16];
        A[0]=row[0];    A[1]=row[256];  A[2]=row[448];  A[3]=row[640];
        A[4]=row[832];  A[5]=row[960];  A[6]=row[1088]; A[7]=row[1216]; A[8]=row[1344];
        A[9]=row[1472]; A[10]=row[1536];A[11]=row[1600];A[12]=row[1664];
        A[13]=row[1728];A[14]=row[1792];A[15]=row[1856];
        ull acc[8];
        #pragma unroll
        for (int i = 0; i < 8; i++) acc[i] = 0ull;
        #pragma unroll
        for (int a = 0; a < 16; a++) {
            #pragma unroll
            for (int b = a; b < 16; b++) {
                const int pi = a*16 - a*(a-1)/2 + (b - a);
                float P = A[a] * A[b];
                ull Pd; PACK2(Pd, P);
                const ulonglong2* c2 = (const ulonglong2*)(sC0 + pi*16);
                ulonglong2 cv0 = c2[0];
                ulonglong2 cv1 = c2[1];
                FMA2(acc[0], Pd, cv0.x); FMA2(acc[1], Pd, cv0.y);
                FMA2(acc[2], Pd, cv1.x); FMA2(acc[3], Pd, cv1.y);
                ulonglong2 cv2 = c2[2];
                ulonglong2 cv3 = c2[3];
                FMA2(acc[4], Pd, cv2.x); FMA2(acc[5], Pd, cv2.y);
                FMA2(acc[6], Pd, cv3.x); FMA2(acc[7], Pd, cv3.y);
            }
        }
        float v[16];
        #pragma unroll
        for (int i = 0; i < 8; i++) UNPK2(v[2*i], v[2*i+1], acc[i]);
        row[0]   =A[0] +0.1f*v[0];  row[256] =A[1] +0.1f*v[1];  row[448] =A[2] +0.1f*v[2];
        row[640] =A[3] +0.1f*v[3];  row[832] =A[4] +0.1f*v[4];  row[960] =A[5] +0.1f*v[5];
        row[1088]=A[6] +0.1f*v[6];  row[1216]=A[7] +0.1f*v[7];  row[1344]=A[8] +0.1f*v[8];
        row[1472]=A[9] +0.1f*v[9];  row[1536]=A[10]+0.1f*v[10]; row[1600]=A[11]+0.1f*v[11];
        row[1664]=A[12]+0.1f*v[12]; row[1728]=A[13]+0.1f*v[13]; row[1792]=A[14]+0.1f*v[14];
        row[1856]=A[15]+0.1f*v[15];
    }
    {
        float* row = rowb + 64 + k;
        float A[9];
        A[0]=row[0];   A[1]=row[256]; A[2]=row[448]; A[3]=row[640];
        A[4]=row[832]; A[5]=row[960]; A[6]=row[1088];A[7]=row[1216];A[8]=row[1344];
        ull acc[4];
        #pragma unroll
        for (int i = 0; i < 4; i++) acc[i] = 0ull;
        float acc8 = 0.f;
        #pragma unroll
        for (int a = 0; a < 9; a++) {
            #pragma unroll
            for (int b = a; b < 9; b++) {
                const int pi = a*9 - a*(a-1)/2 + (b - a);
                float P = A[a] * A[b];
                ull Pd; PACK2(Pd, P);
                const ulonglong2* c2 = (const ulonglong2*)(sC1 + pi*16);
                ulonglong2 cv0 = c2[0];
                ulonglong2 cv1 = c2[1];
                FMA2(acc[0], Pd, cv0.x); FMA2(acc[1], Pd, cv0.y);
                FMA2(acc[2], Pd, cv1.x); FMA2(acc[3], Pd, cv1.y);
                acc8 += P * sC1[pi*16 + 8];
            }
        }
        float v[8];
        #pragma unroll
        for (int i = 0; i < 4; i++) UNPK2(v[2*i], v[2*i+1], acc[i]);
        row[0]   =A[0]+0.1f*v[0]; row[256] =A[1]+0.1f*v[1]; row[448] =A[2]+0.1f*v[2];
        row[640] =A[3]+0.1f*v[3]; row[832] =A[4]+0.1f*v[4]; row[960] =A[5]+0.1f*v[5];
        row[1088]=A[6]+0.1f*v[6]; row[1216]=A[7]+0.1f*v[7]; row[1344]=A[8]+0.1f*acc8;
    }
    {
        float* row = rowb + 128 + k;
        float A[4];
        A[0]=row[0]; A[1]=row[256]; A[2]=row[448]; A[3]=row[640];
        float acc[4] = {0.f, 0.f, 0.f, 0.f};
        #pragma unroll
        for (int a = 0; a < 4; a++) {
            #pragma unroll
            for (int b = a; b < 4; b++) {
                const int pi = a*4 - a*(a-1)/2 + (b - a);
                float P = A[a] * A[b];
                #pragma unroll
                for (int M = 0; M < 4; M++) acc[M] += P * sC2[pi*4 + M];
            }
        }
        row[0]  =A[0]+0.1f*acc[0]; row[256]=A[1]+0.1f*acc[1];
        row[448]=A[2]+0.1f*acc[2]; row[640]=A[3]+0.1f*acc[3];

        float* row3 = rowb + 192 + k;
        float A3 = row3[0];
        row3[0] = A3 + 0.1f * A3 * A3 * sC2[40];
    }
}

// ---------------- equivariant MP v8: b-split roles + 2 pairs per barrier ----------------
// Roles: wl0/1/2 = kb0 blocks {0..5},{6..10},{11..15} for ALL 16 M (partials cross-warp reduced);
// wl3 = kb1+kb2+kb3. W staged non-duplicated, 2 pairs (512 floats) per buffer.

template<int B0,int NB>
__device__ __forceinline__ void kb0body(ull* acc, const float* __restrict__ EF,
                                        const float* w, int lane, ull emb2) {
    #pragma unroll
    for (int bb = 0; bb < NB; bb++) {
        const int b = B0 + bb;
        ull efp = *(const ull*)(EF + OFFS[b] + 2*lane);
        ull v; MUL2(v, efp, emb2);
        float f0, f1; UNPK2(f0, f1, v);
        ull vA, vB; PACK2(vA, f0); PACK2(vB, f1);
        const ulonglong2* wb = (const ulonglong2*)(w + b*16);
        ulonglong2 q0 = wb[0], q1 = wb[1];
        FMA2(acc[0], vA, q0.x); FMA2(acc[1], vA, q0.y);
        FMA2(acc[2], vA, q1.x); FMA2(acc[3], vA, q1.y);
        FMA2(acc[8], vB, q0.x); FMA2(acc[9], vB, q0.y);
        FMA2(acc[10], vB, q1.x); FMA2(acc[11], vB, q1.y);
        ulonglong2 q2 = wb[2], q3 = wb[3];
        FMA2(acc[4], vA, q2.x); FMA2(acc[5], vA, q2.y);
        FMA2(acc[6], vA, q3.x); FMA2(acc[7], vA, q3.y);
        FMA2(acc[12], vB, q2.x); FMA2(acc[13], vB, q2.y);
        FMA2(acc[14], vB, q3.x); FMA2(acc[15], vB, q3.y);
    }
}

__device__ __forceinline__ void kb123body(ull* acc, const float* __restrict__ EF,
                                          const float* w, int lane, ull emb2) {
    #pragma unroll
    for (int b = 0; b < 9; b++) {
        ull efp = *(const ull*)(EF + OFFS[b] + 64 + 2*lane);
        ull v; MUL2(v, efp, emb2);
        float f0, f1; UNPK2(f0, f1, v);
        ull vA, vB; PACK2(vA, f0); PACK2(vB, f1);
        const ulonglong2* wb = (const ulonglong2*)(w + b*16);
        ulonglong2 q0 = wb[0], q1 = wb[1];
        ull w8 = *(const ull*)(w + b*16 + 8);
        FMA2(acc[0], vA, q0.x); FMA2(acc[1], vA, q0.y);
        FMA2(acc[2], vA, q1.x); FMA2(acc[3], vA, q1.y); FMA2(acc[4], vA, w8);
        FMA2(acc[8], vB, q0.x); FMA2(acc[9], vB, q0.y);
        FMA2(acc[10], vB, q1.x); FMA2(acc[11], vB, q1.y); FMA2(acc[12], vB, w8);
    }
    #pragma unroll
    for (int b = 0; b < 4; b++) {
        ull efp = *(const ull*)(EF + OFFS[b] + 128 + 2*lane);
        ull v; MUL2(v, efp, emb2);
        float f0, f1; UNPK2(f0, f1, v);
        ull vA, vB; PACK2(vA, f0); PACK2(vB, f1);
        ulonglong2 q0 = *(const ulonglong2*)(w + b*16);
        FMA2(acc[5], vA, q0.x); FMA2(acc[6], vA, q0.y);
        FMA2(acc[13], vB, q0.x); FMA2(acc[14], vB, q0.y);
    }
    {
        ull efp = *(const ull*)(EF + 192 + 2*lane);
        ull v; MUL2(v, efp, emb2);
        float f0, f1; UNPK2(f0, f1, v);
        ull vA, vB; PACK2(vA, f0); PACK2(vB, f1);
        ull w0 = *(const ull*)(w);
        FMA2(acc[7], vA, w0); FMA2(acc[15], vB, w0);
    }
}

__device__ __forceinline__ void pairBody(ull* acc, int wl, const float* EF,
                                         const float* w, int lane, ull emb2) {
    if      (wl == 0) kb0body<0,6>(acc, EF, w, lane, emb2);
    else if (wl == 1) kb0body<6,5>(acc, EF, w, lane, emb2);
    else if (wl == 2) kb0body<11,5>(acc, EF, w, lane, emb2);
    else              kb123body(acc, EF, w, lane, emb2);
}

__device__ __forceinline__ void stage2W(float* buf, int start, int e0, int cnt, int ht) {
    #pragma unroll
    for (int j = 0; j < 2; j++) {
        float2 v = make_float2(0.f, 0.f);
        if (e0 + j < cnt)
            v = *(const float2*)(g_W + (size_t)(start + e0 + j)*256 + 2*ht);
        *(float2*)(buf + j*256 + 2*ht) = v;
    }
}

__global__ void __launch_bounds__(256, 4) k_eqmp8(int N) {
    __shared__ __align__(16) float sWs[2][2][512];    // [half][buf][pair*256 + col]
    __shared__ __align__(16) ull   sRed[2][2][512];   // [half][warp-1][lane*16 + slot]
    __shared__ int sCtr[2];
    int t = threadIdx.x;
    int half = t >> 7, ht = t & 127;
    int wl = (t >> 5) & 3, lane = t & 31;
    int barid = 1 + half;

    for (;;) {
        if (ht == 0) sCtr[half] = atomicAdd(&g_ctr, 1);
        asm volatile("bar.sync %0, 128;" :: "r"(barid) : "memory");
        int n = sCtr[half];
        if (n >= N) break;
        int start = g_starts[n], cnt = g_counts[n];

        ull acc[16];
        #pragma unroll
        for (int i = 0; i < 16; i++) acc[i] = 0ull;

        if (cnt > 0) {
            stage2W(sWs[half][0], start, 0, cnt, ht);
            asm volatile("bar.sync %0, 128;" :: "r"(barid) : "memory");
            int cur = 0;
            for (int e0 = 0; e0 < cnt; e0 += 2) {
                if (e0 + 2 < cnt) stage2W(sWs[half][cur ^ 1], start, e0 + 2, cnt, ht);
                {
                    int n0 = g_snbr[start + e0];
                    const float* EF0 = g_feats + (size_t)n0 * 1920;
                    ull emb0 = *(const ull*)(g_emb + n0*32 + 2*(lane & 15));
                    pairBody(acc, wl, EF0, sWs[half][cur], lane, emb0);
                }
                if (e0 + 1 < cnt) {
                    int n1 = g_snbr[start + e0 + 1];
                    const float* EF1 = g_feats + (size_t)n1 * 1920;
                    ull emb1 = *(const ull*)(g_emb + n1*32 + 2*(lane & 15));
                    pairBody(acc, wl, EF1, sWs[half][cur] + 256, lane, emb1);
                }
                asm volatile("bar.sync %0, 128;" :: "r"(barid) : "memory");
                cur ^= 1;
            }
        }

        // cross-warp reduction of kb0 partials
        if (wl == 1 || wl == 2) {
            ull* dst = &sRed[half][wl-1][lane*16];
            #pragma unroll
            for (int i = 0; i < 8; i++)
                *(ulonglong2*)(dst + 2*i) = make_ulonglong2(acc[2*i], acc[2*i+1]);
        }
        asm volatile("bar.sync %0, 128;" :: "r"(barid) : "memory");

        float* orow = g_feats2 + (size_t)n * 1920;
        if (wl == 0) {
            const ull* s1 = &sRed[half][0][lane*16];
            const ull* s2 = &sRed[half][1][lane*16];
            #pragma unroll
            for (int i = 0; i < 8; i++) {
                ulonglong2 a = *(const ulonglong2*)(s1 + 2*i);
                ulonglong2 b = *(const ulonglong2*)(s2 + 2*i);
                ADD2(acc[2*i], a.x);   ADD2(acc[2*i+1], a.y);
                ADD2(acc[2*i], b.x);   ADD2(acc[2*i+1], b.y);
            }
            #pragma unroll
            for (int mp = 0; mp < 8; mp++) {
                float a0, a1, b0, b1;
                UNPK2(a0, a1, acc[mp]);
                UNPK2(b0, b1, acc[8+mp]);
                *(float2*)(orow + OFFS[2*mp]   + 2*lane) = make_float2(0.1f*a0, 0.1f*b0);
                *(float2*)(orow + OFFS[2*mp+1] + 2*lane) = make_float2(0.1f*a1, 0.1f*b1);
            }
        } else if (wl == 3) {
            #pragma unroll
            for (int mp = 0; mp < 4; mp++) {
                float a0, a1, b0, b1;
                UNPK2(a0, a1, acc[mp]);
                UNPK2(b0, b1, acc[8+mp]);
                *(float2*)(orow + OFFS[2*mp]   + 64 + 2*lane) = make_float2(0.1f*a0, 0.1f*b0);
                *(float2*)(orow + OFFS[2*mp+1] + 64 + 2*lane) = make_float2(0.1f*a1, 0.1f*b1);
            }
            {
                float a0, ax, b0, bx;
                UNPK2(a0, ax, acc[4]); UNPK2(b0, bx, acc[12]);
                *(float2*)(orow + OFFS[8] + 64 + 2*lane) = make_float2(0.1f*a0, 0.1f*b0);
            }
            #pragma unroll
            for (int mp = 0; mp < 2; mp++) {
                float a0, a1, b0, b1;
                UNPK2(a0, a1, acc[5+mp]);
                UNPK2(b0, b1, acc[13+mp]);
                *(float2*)(orow + OFFS[2*mp]   + 128 + 2*lane) = make_float2(0.1f*a0, 0.1f*b0);
                *(float2*)(orow + OFFS[2*mp+1] + 128 + 2*lane) = make_float2(0.1f*a1, 0.1f*b1);
            }
            {
                float a0, ax, b0, bx;
                UNPK2(a0, ax, acc[7]); UNPK2(b0, bx, acc[15]);
                *(float2*)(orow + 192 + 2*lane) = make_float2(0.1f*a0, 0.1f*b0);
            }
        }
    }
}

// ---------------- final TP (M=0 only) fused with energy readout ----------------
__global__ void __launch_bounds__(256) k_tpE(const float* __restrict__ wE,
                                             const float* __restrict__ bE,
                                             float* __restrict__ out, int N) {
    __shared__ float sC0[136];
    __shared__ float sC1[45];
    __shared__ float sC2[11];
    __shared__ float sred[8];
    int t = threadIdx.x;
    for (int i = t; i < 136; i += 256) sC0[i] = g_sym0[i*16];
    if (t < 45) sC1[t] = g_sym1[t*16];
    if (t < 10) sC2[t] = g_sym2[t*4];
    if (t == 10) sC2[10] = g_c000[0];
    __syncthreads();
    int atom = blockIdx.x * 4 + (t >> 6);
    int k = t & 63;
    float e = 0.f;
    if (atom < N) {
        const float* rowb = g_feats2 + (size_t)atom * 1920;
        float L0_0, L0_1, L0_2, L0_3;
        {
            const float* row = rowb + k;
            float A[16];
            A[0]=row[0];    A[1]=row[256];  A[2]=row[448];  A[3]=row[640];
            A[4]=row[832];  A[5]=row[960];  A[6]=row[1088]; A[7]=row[1216]; A[8]=row[1344];
            A[9]=row[1472]; A[10]=row[1536];A[11]=row[1600];A[12]=row[1664];
            A[13]=row[1728];A[14]=row[1792];A[15]=row[1856];
            float acc = 0.f;
            #pragma unroll
            for (int a = 0; a < 16; a++) {
                #pragma unroll
                for (int b = a; b < 16; b++) {
                    const int pi = a*16 - a*(a-1)/2 + (b - a);
                    acc += A[a] * A[b] * sC0[pi];
                }
            }
            L0_0 = A[0] + 0.1f * acc;
        }
        {
            const float* row = rowb + 64 + k;
            float A[9];
            A[0]=row[0];   A[1]=row[256]; A[2]=row[448]; A[3]=row[640];
            A[4]=row[832]; A[5]=row[960]; A[6]=row[1088];A[7]=row[1216];A[8]=row[1344];
            float acc = 0.f;
            #pragma unroll
            for (int a = 0; a < 9; a++) {
                #pragma unroll
                for (int b = a; b < 9; b++) {
                    const int pi = a*9 - a*(a-1)/2 + (b - a);
                    acc += A[a] * A[b] * sC1[pi];
                }
            }
            L0_1 = A[0] + 0.1f * acc;
        }
        {
            const float* row = rowb + 128 + k;
            float A[4];
            A[0]=row[0]; A[1]=row[256]; A[2]=row[448]; A[3]=row[640];
            float acc = 0.f;
            #pragma unroll
            for (int a = 0; a < 4; a++) {
                #pragma unroll
                for (int b = a; b < 4; b++) {
                    const int pi = a*4 - a*(a-1)/2 + (b - a);
                    acc += A[a] * A[b] * sC2[pi];
                }
            }
            L0_2 = A[0] + 0.1f * acc;
        }
        {
            float A3 = rowb[192 + k];
            L0_3 = A3 + 0.1f * A3 * A3 * sC2[10];
        }
        float embc = g_emb[atom*32 + (k & 31)];
        e = embc * (L0_0 * wE[k] + L0_1 * wE[64+k] + L0_2 * wE[128+k] + L0_3 * wE[192+k]);
    }
    #pragma unroll
    for (int o = 16; o > 0; o >>= 1) e += __shfl_xor_sync(0xffffffffu, e, o);
    if ((t & 31) == 0) sred[t >> 5] = e;
    __syncthreads();
    if ((t & 63) == 0 && atom < N)
        out[atom] = sred[t >> 5] + sred[(t >> 5) + 1] + bE[0];
}

// ---------------- host: numpy RandomState(0).randn ----------------
static void gen_cg(float* out) {
    static uint32_t mt[624];
    int mti;
    mt[0] = 0;
    for (int i = 1; i < 624; i++)
        mt[i] = 1812433253u * (mt[i-1] ^ (mt[i-1] >> 30)) + (uint32_t)i;
    mti = 624;
    auto genrand = [&]() -> uint32_t {
        if (mti >= 624) {
            for (int i = 0; i < 624; i++) {
                uint32_t y = (mt[i] & 0x80000000u) | (mt[(i+1) % 624] & 0x7fffffffu);
                mt[i] = mt[(i+397) % 624] ^ (y >> 1) ^ ((y & 1u) ? 2567483615u : 0u);
            }
            mti = 0;
        }
        uint32_t y = mt[mti++];
        y ^= y >> 11; y ^= (y << 7) & 2636928640u; y ^= (y << 15) & 4022730752u; y ^= y >> 18;
        return y;
    };
    auto rdouble = [&]() -> double {
        uint32_t a = genrand() >> 5, b = genrand() >> 6;
        return (a * 67108864.0 + b) / 9007199254740992.0;
    };
    bool has_g = false; double gcache = 0.0;
    auto gauss = [&]() -> double {
        if (has_g) { has_g = false; return gcache; }
        double x1, x2, r2;
        do {
            x1 = 2.0 * rdouble() - 1.0;
            x2 = 2.0 * rdouble() - 1.0;
            r2 = x1*x1 + x2*x2;
        } while (r2 >= 1.0 || r2 == 0.0);
        double f = sqrt(-2.0 * log(r2) / r2);
        gcache = f * x1; has_g = true;
        return f * x2;
    };
    for (int i = 0; i < 3436; i++) out[i] = (float)(gauss() * 0.2);
}

static CGBuf h_cg;

// Persistent side stream + events for graph-captured fork/join.
static cudaStream_t g_s2 = nullptr;
static cudaEvent_t  g_evFork = nullptr, g_evJoin = nullptr;

extern "C" void kernel_launch(void* const* d_in, const int* in_sizes, int n_in,
                              void* d_out, int out_size) {
    const float* sh      = (const float*)d_in[0];
    const float* rb      = (const float*)d_in[1];
    const float* tab     = (const float*)d_in[2];
    const float* wE      = (const float*)d_in[3];
    const float* bE      = (const float*)d_in[4];
    const int*   spec    = (const int*)d_in[5];
    const int*   centers = (const int*)d_in[6];
    const int*   nbrs    = (const int*)d_in[7];
    int N = in_sizes[5];
    int P = in_sizes[6];
    float* out = (float*)d_out;

    if (g_s2 == nullptr) {
        cudaStreamCreateWithFlags(&g_s2, cudaStreamNonBlocking);
        cudaEventCreateWithFlags(&g_evFork, cudaEventDisableTiming);
        cudaEventCreateWithFlags(&g_evJoin, cudaEventDisableTiming);
    }

    gen_cg(h_cg.v);

    // Chain head (default stream): CG tables + init
    k_initcg<<<1, 256>>>(h_cg);
    k_misc1<<<(N*240 + 255)/256, 256>>>(tab, spec, N);

    // Fork: chain B (invariant MP + first TP) on side stream
    cudaEventRecord(g_evFork, 0);
    cudaStreamWaitEvent(g_s2, g_evFork, 0);
    k_invA<<<(P*64 + 255)/256, 256, 0, g_s2>>>(sh, rb, centers, nbrs, spec, P);
    k_invB<<<N, 256, 0, g_s2>>>(tab, N);
    k_tpA<<<(N + 3)/4, 256, 0, g_s2>>>(N);
    cudaEventRecord(g_evJoin, g_s2);

    // Chain A (default stream): counting sort + per-pair W
    k_hist<<<(P + 255)/256, 256>>>(centers, P);
    k_scan<<<1, 1024>>>(N);
    k_scatter<<<(P + 255)/256, 256>>>(centers, P);
    k_Wb<<<(P + 7)/8, 256>>>(sh, rb, nbrs, P);

    // Join, then message passing + energy
    cudaStreamWaitEvent(0, g_evJoin, 0);
    k_eqmp8<<<592, 256>>>(N);
    k_tpE<<<(N + 3)/4, 256>>>(wE, bE, out, N);
}

// round 17
// speedup vs baseline: 1.0616x; 1.0616x over previous
#include <cuda_runtime.h>
#include <cstdint>
#include <math.h>

#define NMAXA 8192
#define PMAXP 131072

typedef unsigned long long ull;

// ---------------- device scratch ----------------
__device__ float g_cgw[4096];                      // dense CG [aF][bF*16+MF]
__device__ float g_sym0[136 * 16];
__device__ float g_sym1[45 * 16];
__device__ float g_sym2[10 * 4];
__device__ float g_c000[1];
__device__ float g_emb[NMAXA * 32];
__device__ float g_feats[(size_t)NMAXA * 1920];
__device__ float g_feats2[(size_t)NMAXA * 1920];
__device__ float g_S[NMAXA * 240];
__device__ float g_W[(size_t)PMAXP * 256];         // per-pair W (ORIGINAL pair order)
__device__ int   g_snbr[PMAXP];
__device__ int   g_counts[NMAXA];
__device__ int   g_starts[NMAXA];
__device__ int   g_cursor[NMAXA];
__device__ int   g_sorted[PMAXP];
__device__ int   g_ctr;

struct CGBuf { float v[3436]; };

__device__ __forceinline__ int shoff(int l) { return l==0?0:l==1?1:l==2?4:9; }

__device__ constexpr int OFFS[16] = {0,256,448,640,832,960,1088,1216,1344,
                                     1472,1536,1600,1664,1728,1792,1856};

__constant__ int c_e_l1[34]={0,0,0,0, 1,1,1,1,1,1,1,1,1, 2,2,2,2,2,2,2,2,2,2,2, 3,3,3,3,3,3,3,3,3,3};
__constant__ int c_e_l2[34]={0,1,2,3, 0,1,1,1,2,2,2,3,3, 0,1,1,1,2,2,2,2,3,3,3, 0,1,1,2,2,2,3,3,3,3};
__constant__ int c_e_L [34]={0,1,2,3, 1,0,1,2,1,2,3,2,3, 2,1,2,3,0,1,2,3,1,2,3, 3,2,3,1,2,3,0,1,2,3};
__constant__ int c_e_off[34]={0,1,10,35, 84,93,102,129,174,219,294,399,504,
                              651,676,721,796,901,926,1001,1126,1301,1406,1581,
                              1826,1875,1980,2127,2232,2407,2652,2701,2848,3093};

#define FMA2(ACC,PD,CV) asm("fma.rn.f32x2 %0, %1, %2, %0;" : "+l"(ACC) : "l"(PD), "l"(CV))
#define MUL2(OUT,A,B)   asm("mul.rn.f32x2 %0, %1, %2;" : "=l"(OUT) : "l"(A), "l"(B))
#define PACK2(PD,P)     asm("mov.b64 %0, {%1, %1};" : "=l"(PD) : "f"(P))
#define UNPK2(LO,HI,PD) asm("mov.b64 {%0, %1}, %2;" : "=f"(LO), "=f"(HI) : "l"(PD))

// ---------------- CG build ----------------
__global__ void k_initcg(CGBuf cg) {
    int t = threadIdx.x;
    for (int i = t; i < 4096; i += 256) g_cgw[i] = 0.f;
    __syncthreads();
    for (int e = 0; e < 34; e++) {
        int l1 = c_e_l1[e], l2 = c_e_l2[e], L = c_e_L[e];
        int d2 = 2*l2+1, dL = 2*L+1;
        int sz = (2*l1+1)*d2*dL, off = c_e_off[e];
        for (int i = t; i < sz; i += 256) {
            int M = i % dL; int r = i / dL; int b = r % d2; int a = r / d2;
            g_cgw[(shoff(l1)+a)*256 + (shoff(l2)+b)*16 + shoff(L)+M] = cg.v[off + i];
        }
        __syncthreads();
    }
    for (int i = t; i < 136*16; i += 256) {
        int pi = i >> 4, M = i & 15;
        int a = 0, base = 0;
        while (base + (16 - a) <= pi) { base += 16 - a; a++; }
        int b = a + (pi - base);
        float v = g_cgw[a*256 + b*16 + M];
        if (a != b) v += g_cgw[b*256 + a*16 + M];
        g_sym0[i] = v;
    }
    for (int i = t; i < 45*16; i += 256) {
        int pi = i >> 4, M = i & 15;
        int a = 0, base = 0;
        while (base + (9 - a) <= pi) { base += 9 - a; a++; }
        int b = a + (pi - base);
        float v = 0.f;
        if (M < 9) {
            v = g_cgw[a*256 + b*16 + M];
            if (a != b) v += g_cgw[b*256 + a*16 + M];
        }
        g_sym1[i] = v;
    }
    for (int i = t; i < 40; i += 256) {
        int pi = i >> 2, M = i & 3;
        int a = 0, base = 0;
        while (base + (4 - a) <= pi) { base += 4 - a; a++; }
        int b = a + (pi - base);
        float v = g_cgw[a*256 + b*16 + M];
        if (a != b) v += g_cgw[b*256 + a*16 + M];
        g_sym2[i] = v;
    }
    if (t == 0) g_c000[0] = g_cgw[0];
}

// ---------------- embeddings, counting sort ----------------
__global__ void k_misc1(const float* __restrict__ tab, const int* __restrict__ spec, int N) {
    int i = blockIdx.x * blockDim.x + threadIdx.x;
    if (i == 0) g_ctr = 0;
    if (i < N * 32) g_emb[i] = tab[spec[i >> 5] * 32 + (i & 31)];
    if (i < N) g_counts[i] = 0;
    if (i < N * 240) g_S[i] = 0.f;
}

__global__ void k_hist(const int* __restrict__ centers, int P) {
    int p = blockIdx.x * blockDim.x + threadIdx.x;
    if (p < P) atomicAdd(&g_counts[centers[p]], 1);
}

__global__ void __launch_bounds__(1024) k_scan(int N) {
    __shared__ int wsum[32];
    int t = threadIdx.x;
    int lane = t & 31, wid = t >> 5;
    int base = t * 8;
    int v[8]; int s = 0;
    #pragma unroll
    for (int j = 0; j < 8; j++) {
        v[j] = (base + j < N) ? g_counts[base + j] : 0;
        s += v[j];
    }
    int ps = s;
    #pragma unroll
    for (int o = 1; o < 32; o <<= 1) {
        int u = __shfl_up_sync(0xffffffffu, ps, o);
        if (lane >= o) ps += u;
    }
    if (lane == 31) wsum[wid] = ps;
    __syncthreads();
    if (wid == 0) {
        int w = wsum[lane];
        int pw = w;
        #pragma unroll
        for (int o = 1; o < 32; o <<= 1) {
            int u = __shfl_up_sync(0xffffffffu, pw, o);
            if (lane >= o) pw += u;
        }
        wsum[lane] = pw - w;
    }
    __syncthreads();
    int ex = wsum[wid] + ps - s;
    #pragma unroll
    for (int j = 0; j < 8; j++) {
        if (base + j < N) { g_starts[base + j] = ex; g_cursor[base + j] = ex; }
        ex += v[j];
    }
}

// scatter also records neighbor per sorted position
__global__ void k_scatter(const int* __restrict__ centers,
                          const int* __restrict__ neighbors, int P) {
    int p = blockIdx.x * blockDim.x + threadIdx.x;
    if (p < P) {
        int pos = atomicAdd(&g_cursor[centers[p]], 1);
        g_sorted[pos] = p;
        g_snbr[pos] = neighbors[p];
    }
}

// ---------------- per-pair W precompute, ORIGINAL order (no sort dependency) ----------------
__global__ void __launch_bounds__(256) k_Wb2(const float* __restrict__ sh,
                                             const float* __restrict__ rb, int P) {
    __shared__ float sEp[16][8];
    int t = threadIdx.x;
    int p0 = blockIdx.x * 8;
    if (t < 128) {
        int pb = t >> 4, a = t & 15;
        int p = p0 + pb;
        float e = 0.f;
        if (p < P) {
            int l   = (a==0)?0:(a<4)?1:(a<9)?2:3;
            int nrl = (l==0?8:l==1?6:l==2?4:2);
            int rbo = (l==0?0:l==1?8:l==2?14:18);
            float s = 0.f;
            for (int r = 0; r < nrl; r++) s += rb[p*20 + rbo + r];
            e = sh[p*16 + a] * 0.1f * s;
        }
        sEp[a][pb] = e;
    }
    ull cA[16];
    #pragma unroll
    for (int a = 0; a < 16; a++) { float c = g_cgw[a*256 + t]; PACK2(cA[a], c); }
    __syncthreads();
    #pragma unroll
    for (int i = 0; i < 4; i++) {
        ull acc = 0ull;
        #pragma unroll
        for (int a = 0; a < 16; a++) {
            ull e2 = *(const ull*)(&sEp[a][2*i]);
            FMA2(acc, e2, cA[a]);
        }
        float v0, v1; UNPK2(v0, v1, acc);
        int p = p0 + 2*i;
        if (p < P)     g_W[(size_t)p*256 + t]     = v0;
        if (p + 1 < P) g_W[(size_t)(p+1)*256 + t] = v1;
    }
}

// ---------------- invariant MP ----------------
__global__ void k_invA(const float* __restrict__ sh, const float* __restrict__ rb,
                       const int* __restrict__ centers, const int* __restrict__ neighbors,
                       const int* __restrict__ spec, int P) {
    int idx = blockIdx.x * blockDim.x + threadIdx.x;
    int p = idx >> 6, j = idx & 63;
    if (p >= P || j >= 60) return;
    int l, m, nr;
    if (j < 8)       { l = 0; m = 0;        nr = j; }
    else if (j < 26) { l = 1; int r = j-8;  m = r/6; nr = r%6; }
    else if (j < 46) { l = 2; int r = j-26; m = r/4; nr = r%4; }
    else             { l = 3; int r = j-46; m = r/2; nr = r%2; }
    int shf = shoff(l) + m;
    int rbf = (l==0?0:l==1?8:l==2?14:18) + nr;
    float val = sh[p*16 + shf] * 0.1f * rb[p*20 + rbf];
    int s = spec[neighbors[p]];
    atomicAdd(&g_S[(centers[p]*4 + s)*60 + j], val);
}

__global__ void __launch_bounds__(256) k_invB(const float* __restrict__ tab, int N) {
    int n = blockIdx.x, t = threadIdx.x;
    #pragma unroll
    for (int j = 0; j < 8; j++) {
        int f = j*256 + t;
        if (f >= 1920) break;
        int l, m, k;
        if (f < 256)       { l = 0; m = 0;         k = f; }
        else if (f < 832)  { int r = f-256; l = 1; m = r/192; k = r - m*192; }
        else if (f < 1472) { int r = f-832; l = 2; m = r>>7;  k = r & 127; }
        else               { int r = f-1472;l = 3; m = r>>6;  k = r & 63; }
        int nr = k >> 5, c = k & 31;
        int nrl = (l==0?8:l==1?6:l==2?4:2);
        int jb  = (l==0?0:l==1?8:l==2?26:46);
        int jj = jb + m*nrl + nr;
        const float* Sp = &g_S[n*240 + jj];
        float s = 0.f;
        #pragma unroll
        for (int sp = 0; sp < 4; sp++) s += Sp[sp*60] * tab[sp*32 + c];
        g_feats[(size_t)n*1920 + f] = 0.1f * s;
    }
}

// ---------------- unified tensor product (layer 1) ----------------
__global__ void __launch_bounds__(256) k_tpA(int N) {
    __shared__ float sC0[136 * 16];
    __shared__ float sC1[45 * 16];
    __shared__ float sC2[44];
    int t = threadIdx.x;
    for (int i = t; i < 2176; i += 256) sC0[i] = g_sym0[i];
    for (int i = t; i < 720; i += 256) sC1[i] = g_sym1[i];
    if (t < 40) sC2[t] = g_sym2[t];
    if (t == 40) sC2[40] = g_c000[0];
    __syncthreads();
    int atom = blockIdx.x * 4 + (t >> 6);
    if (atom >= N) return;
    int k = t & 63;
    float* rowb = g_feats + (size_t)atom * 1920;

    {
        float* row = rowb + k;
        float A[16];
        A[0]=row[0];    A[1]=row[256];  A[2]=row[448];  A[3]=row[640];
        A[4]=row[832];  A[5]=row[960];  A[6]=row[1088]; A[7]=row[1216]; A[8]=row[1344];
        A[9]=row[1472]; A[10]=row[1536];A[11]=row[1600];A[12]=row[1664];
        A[13]=row[1728];A[14]=row[1792];A[15]=row[1856];
        ull acc[8];
        #pragma unroll
        for (int i = 0; i < 8; i++) acc[i] = 0ull;
        #pragma unroll
        for (int a = 0; a < 16; a++) {
            #pragma unroll
            for (int b = a; b < 16; b++) {
                const int pi = a*16 - a*(a-1)/2 + (b - a);
                float P = A[a] * A[b];
                ull Pd; PACK2(Pd, P);
                const ulonglong2* c2 = (const ulonglong2*)(sC0 + pi*16);
                ulonglong2 cv0 = c2[0];
                ulonglong2 cv1 = c2[1];
                FMA2(acc[0], Pd, cv0.x); FMA2(acc[1], Pd, cv0.y);
                FMA2(acc[2], Pd, cv1.x); FMA2(acc[3], Pd, cv1.y);
                ulonglong2 cv2 = c2[2];
                ulonglong2 cv3 = c2[3];
                FMA2(acc[4], Pd, cv2.x); FMA2(acc[5], Pd, cv2.y);
                FMA2(acc[6], Pd, cv3.x); FMA2(acc[7], Pd, cv3.y);
            }
        }
        float v[16];
        #pragma unroll
        for (int i = 0; i < 8; i++) UNPK2(v[2*i], v[2*i+1], acc[i]);
        row[0]   =A[0] +0.1f*v[0];  row[256] =A[1] +0.1f*v[1];  row[448] =A[2] +0.1f*v[2];
        row[640] =A[3] +0.1f*v[3];  row[832] =A[4] +0.1f*v[4];  row[960] =A[5] +0.1f*v[5];
        row[1088]=A[6] +0.1f*v[6];  row[1216]=A[7] +0.1f*v[7];  row[1344]=A[8] +0.1f*v[8];
        row[1472]=A[9] +0.1f*v[9];  row[1536]=A[10]+0.1f*v[10]; row[1600]=A[11]+0.1f*v[11];
        row[1664]=A[12]+0.1f*v[12]; row[1728]=A[13]+0.1f*v[13]; row[1792]=A[14]+0.1f*v[14];
        row[1856]=A[15]+0.1f*v[15];
    }
    {
        float* row = rowb + 64 + k;
        float A[9];
        A[0]=row[0];   A[1]=row[256]; A[2]=row[448]; A[3]=row[640];
        A[4]=row[832]; A[5]=row[960]; A[6]=row[1088];A[7]=row[1216];A[8]=row[1344];
        ull acc[4];
        #pragma unroll
        for (int i = 0; i < 4; i++) acc[i] = 0ull;
        float acc8 = 0.f;
        #pragma unroll
        for (int a = 0; a < 9; a++) {
            #pragma unroll
            for (int b = a; b < 9; b++) {
                const int pi = a*9 - a*(a-1)/2 + (b - a);
                float P = A[a] * A[b];
                ull Pd; PACK2(Pd, P);
                const ulonglong2* c2 = (const ulonglong2*)(sC1 + pi*16);
                ulonglong2 cv0 = c2[0];
                ulonglong2 cv1 = c2[1];
                FMA2(acc[0], Pd, cv0.x); FMA2(acc[1], Pd, cv0.y);
                FMA2(acc[2], Pd, cv1.x); FMA2(acc[3], Pd, cv1.y);
                acc8 += P * sC1[pi*16 + 8];
            }
        }
        float v[8];
        #pragma unroll
        for (int i = 0; i < 4; i++) UNPK2(v[2*i], v[2*i+1], acc[i]);
        row[0]   =A[0]+0.1f*v[0]; row[256] =A[1]+0.1f*v[1]; row[448] =A[2]+0.1f*v[2];
        row[640] =A[3]+0.1f*v[3]; row[832] =A[4]+0.1f*v[4]; row[960] =A[5]+0.1f*v[5];
        row[1088]=A[6]+0.1f*v[6]; row[1216]=A[7]+0.1f*v[7]; row[1344]=A[8]+0.1f*acc8;
    }
    {
        float* row = rowb + 128 + k;
        float A[4];
        A[0]=row[0]; A[1]=row[256]; A[2]=row[448]; A[3]=row[640];
        float acc[4] = {0.f, 0.f, 0.f, 0.f};
        #pragma unroll
        for (int a = 0; a < 4; a++) {
            #pragma unroll
            for (int b = a; b < 4; b++) {
                const int pi = a*4 - a*(a-1)/2 + (b - a);
                float P = A[a] * A[b];
                #pragma unroll
                for (int M = 0; M < 4; M++) acc[M] += P * sC2[pi*4 + M];
            }
        }
        row[0]  =A[0]+0.1f*acc[0]; row[256]=A[1]+0.1f*acc[1];
        row[448]=A[2]+0.1f*acc[2]; row[640]=A[3]+0.1f*acc[3];

        float* row3 = rowb + 192 + k;
        float A3 = row3[0];
        row3[0] = A3 + 0.1f * A3 * A3 * sC2[40];
    }
}

// ---------------- equivariant MP (eqmp3): persistent, dynamic, 2 pairs/barrier ----------------
template<int MF0,int NMF,int B0,int CH,int COLBASE>
__device__ __forceinline__ void roleChunk2(ull* acc,
        const float* __restrict__ EF0, const float* __restrict__ EF1,
        const float* w0, const float* w1,
        int lane, ull emb0, ull emb1) {
    ull ef0[CH], ef1[CH];
    #pragma unroll
    for (int b = 0; b < CH; b++) {
        ef0[b] = *(const ull*)(EF0 + OFFS[B0+b] + COLBASE + 2*lane);
        ef1[b] = *(const ull*)(EF1 + OFFS[B0+b] + COLBASE + 2*lane);
    }
    #pragma unroll
    for (int b = 0; b < CH; b++) {
        ull v0, v1; MUL2(v0, ef0[b], emb0); MUL2(v1, ef1[b], emb1);
        #pragma unroll
        for (int mp = 0; mp < NMF/2; mp++) {
            ulonglong2 wa = *(const ulonglong2*)(w0 + 2*((B0+b)*16 + MF0 + 2*mp));
            FMA2(acc[2*mp], v0, wa.x); FMA2(acc[2*mp+1], v0, wa.y);
            ulonglong2 wb = *(const ulonglong2*)(w1 + 2*((B0+b)*16 + MF0 + 2*mp));
            FMA2(acc[2*mp], v1, wb.x); FMA2(acc[2*mp+1], v1, wb.y);
        }
        if (NMF & 1) {
            ull wa = *(const ull*)(w0 + 2*((B0+b)*16 + MF0 + NMF - 1));
            FMA2(acc[NMF-1], v0, wa);
            ull wb = *(const ull*)(w1 + 2*((B0+b)*16 + MF0 + NMF - 1));
            FMA2(acc[NMF-1], v1, wb);
        }
    }
}

template<int MF0,int NMF,int NB,int COLBASE>
__device__ __forceinline__ void roleFMA2p(ull* acc,
        const float* __restrict__ EF0, const float* __restrict__ EF1,
        const float* w0, const float* w1, int lane, ull emb0, ull emb1) {
    if constexpr (NB == 16) {
        roleChunk2<MF0,NMF,0,4,COLBASE>(acc, EF0, EF1, w0, w1, lane, emb0, emb1);
        roleChunk2<MF0,NMF,4,4,COLBASE>(acc, EF0, EF1, w0, w1, lane, emb0, emb1);
        roleChunk2<MF0,NMF,8,4,COLBASE>(acc, EF0, EF1, w0, w1, lane, emb0, emb1);
        roleChunk2<MF0,NMF,12,4,COLBASE>(acc, EF0, EF1, w0, w1, lane, emb0, emb1);
    } else if constexpr (NB == 9) {
        roleChunk2<MF0,NMF,0,4,COLBASE>(acc, EF0, EF1, w0, w1, lane, emb0, emb1);
        roleChunk2<MF0,NMF,4,4,COLBASE>(acc, EF0, EF1, w0, w1, lane, emb0, emb1);
        roleChunk2<MF0,NMF,8,1,COLBASE>(acc, EF0, EF1, w0, w1, lane, emb0, emb1);
    } else {
        roleChunk2<MF0,NMF,0,NB,COLBASE>(acc, EF0, EF1, w0, w1, lane, emb0, emb1);
    }
}

template<int MF0,int NMF,int COLBASE>
__device__ __forceinline__ void roleStore(const ull* acc, float* orow, int lane) {
    #pragma unroll
    for (int mf = 0; mf < NMF; mf++) {
        float lo, hi; UNPK2(lo, hi, acc[mf]);
        *(float2*)(orow + OFFS[MF0+mf] + COLBASE + 2*lane) = make_float2(0.1f*lo, 0.1f*hi);
    }
}

__device__ __forceinline__ void stage2(float* buf, int start, int e0, int cnt, int ht) {
    #pragma unroll
    for (int j = 0; j < 2; j++) {
        float2 v = make_float2(0.f, 0.f);
        if (e0 + j < cnt) {
            int p = g_sorted[start + e0 + j];          // broadcast load
            v = *(const float2*)(g_W + (size_t)p*256 + 2*ht);
        }
        *(float4*)(buf + j*512 + 4*ht) = make_float4(v.x, v.x, v.y, v.y);
    }
}

__global__ void __launch_bounds__(256, 4) k_eqmp3(int N) {
    __shared__ float sW[2][2][1024];
    __shared__ int sCtr[2];
    int t = threadIdx.x;
    int half = t >> 7, ht = t & 127;
    int wl = (t >> 5) & 3, lane = t & 31;
    int barid = 1 + half;

    for (;;) {
        if (ht == 0) sCtr[half] = atomicAdd(&g_ctr, 1);
        asm volatile("bar.sync %0, 128;" :: "r"(barid) : "memory");
        int n = sCtr[half];
        if (n >= N) break;
        int start = g_starts[n], cnt = g_counts[n];

        ull A[9];
        #pragma unroll
        for (int i = 0; i < 9; i++) A[i] = 0ull;

        if (cnt > 0) {
            stage2(sW[half][0], start, 0, cnt, ht);
            asm volatile("bar.sync %0, 128;" :: "r"(barid) : "memory");
            int cur = 0;
            for (int e0 = 0; e0 < cnt; e0 += 2) {
                if (e0 + 2 < cnt) stage2(sW[half][cur ^ 1], start, e0 + 2, cnt, ht);
                int n0 = g_snbr[start + e0];
                int n1 = (e0 + 1 < cnt) ? g_snbr[start + e0 + 1] : n0;
                const float* EF0 = g_feats + (size_t)n0 * 1920;
                const float* EF1 = g_feats + (size_t)n1 * 1920;
                ull emb0 = *(const ull*)(g_emb + n0*32 + 2*(lane & 15));
                ull emb1 = *(const ull*)(g_emb + n1*32 + 2*(lane & 15));
                const float* w0 = sW[half][cur];
                const float* w1 = sW[half][cur] + 512;
                if      (wl == 0) roleFMA2p<0,6,16,0>(A, EF0, EF1, w0, w1, lane, emb0, emb1);
                else if (wl == 1) roleFMA2p<6,6,16,0>(A, EF0, EF1, w0, w1, lane, emb0, emb1);
                else if (wl == 2) { roleFMA2p<12,4,16,0>(A,   EF0, EF1, w0, w1, lane, emb0, emb1);
                                    roleFMA2p<0,4,4,128>(A+4, EF0, EF1, w0, w1, lane, emb0, emb1);
                                    roleFMA2p<0,1,1,192>(A+8, EF0, EF1, w0, w1, lane, emb0, emb1); }
                else              roleFMA2p<0,9,9,64>(A, EF0, EF1, w0, w1, lane, emb0, emb1);
                asm volatile("bar.sync %0, 128;" :: "r"(barid) : "memory");
                cur ^= 1;
            }
        }

        float* orow = g_feats2 + (size_t)n * 1920;
        if      (wl == 0) roleStore<0,6,0>(A, orow, lane);
        else if (wl == 1) roleStore<6,6,0>(A, orow, lane);
        else if (wl == 2) { roleStore<12,4,0>(A,   orow, lane);
                            roleStore<0,4,128>(A+4, orow, lane);
                            roleStore<0,1,192>(A+8, orow, lane); }
        else              roleStore<0,9,64>(A, orow, lane);
    }
}

// ---------------- final TP (M=0 only) fused with energy readout ----------------
__global__ void __launch_bounds__(256) k_tpE(const float* __restrict__ wE,
                                             const float* __restrict__ bE,
                                             float* __restrict__ out, int N) {
    __shared__ float sC0[136];
    __shared__ float sC1[45];
    __shared__ float sC2[11];
    __shared__ float sred[8];
    int t = threadIdx.x;
    for (int i = t; i < 136; i += 256) sC0[i] = g_sym0[i*16];
    if (t < 45) sC1[t] = g_sym1[t*16];
    if (t < 10) sC2[t] = g_sym2[t*4];
    if (t == 10) sC2[10] = g_c000[0];
    __syncthreads();
    int atom = blockIdx.x * 4 + (t >> 6);
    int k = t & 63;
    float e = 0.f;
    if (atom < N) {
        const float* rowb = g_feats2 + (size_t)atom * 1920;
        float L0_0, L0_1, L0_2, L0_3;
        {
            const float* row = rowb + k;
            float A[16];
            A[0]=row[0];    A[1]=row[256];  A[2]=row[448];  A[3]=row[640];
            A[4]=row[832];  A[5]=row[960];  A[6]=row[1088]; A[7]=row[1216]; A[8]=row[1344];
            A[9]=row[1472]; A[10]=row[1536];A[11]=row[1600];A[12]=row[1664];
            A[13]=row[1728];A[14]=row[1792];A[15]=row[1856];
            float acc = 0.f;
            #pragma unroll
            for (int a = 0; a < 16; a++) {
                #pragma unroll
                for (int b = a; b < 16; b++) {
                    const int pi = a*16 - a*(a-1)/2 + (b - a);
                    acc += A[a] * A[b] * sC0[pi];
                }
            }
            L0_0 = A[0] + 0.1f * acc;
        }
        {
            const float* row = rowb + 64 + k;
            float A[9];
            A[0]=row[0];   A[1]=row[256]; A[2]=row[448]; A[3]=row[640];
            A[4]=row[832]; A[5]=row[960]; A[6]=row[1088];A[7]=row[1216];A[8]=row[1344];
            float acc = 0.f;
            #pragma unroll
            for (int a = 0; a < 9; a++) {
                #pragma unroll
                for (int b = a; b < 9; b++) {
                    const int pi = a*9 - a*(a-1)/2 + (b - a);
                    acc += A[a] * A[b] * sC1[pi];
                }
            }
            L0_1 = A[0] + 0.1f * acc;
        }
        {
            const float* row = rowb + 128 + k;
            float A[4];
            A[0]=row[0]; A[1]=row[256]; A[2]=row[448]; A[3]=row[640];
            float acc = 0.f;
            #pragma unroll
            for (int a = 0; a < 4; a++) {
                #pragma unroll
                for (int b = a; b < 4; b++) {
                    const int pi = a*4 - a*(a-1)/2 + (b - a);
                    acc += A[a] * A[b] * sC2[pi];
                }
            }
            L0_2 = A[0] + 0.1f * acc;
        }
        {
            float A3 = rowb[192 + k];
            L0_3 = A3 + 0.1f * A3 * A3 * sC2[10];
        }
        float embc = g_emb[atom*32 + (k & 31)];
        e = embc * (L0_0 * wE[k] + L0_1 * wE[64+k] + L0_2 * wE[128+k] + L0_3 * wE[192+k]);
    }
    #pragma unroll
    for (int o = 16; o > 0; o >>= 1) e += __shfl_xor_sync(0xffffffffu, e, o);
    if ((t & 31) == 0) sred[t >> 5] = e;
    __syncthreads();
    if ((t & 63) == 0 && atom < N)
        out[atom] = sred[t >> 5] + sred[(t >> 5) + 1] + bE[0];
}

// ---------------- host: numpy RandomState(0).randn ----------------
static void gen_cg(float* out) {
    static uint32_t mt[624];
    int mti;
    mt[0] = 0;
    for (int i = 1; i < 624; i++)
        mt[i] = 1812433253u * (mt[i-1] ^ (mt[i-1] >> 30)) + (uint32_t)i;
    mti = 624;
    auto genrand = [&]() -> uint32_t {
        if (mti >= 624) {
            for (int i = 0; i < 624; i++) {
                uint32_t y = (mt[i] & 0x80000000u) | (mt[(i+1) % 624] & 0x7fffffffu);
                mt[i] = mt[(i+397) % 624] ^ (y >> 1) ^ ((y & 1u) ? 2567483615u : 0u);
            }
            mti = 0;
        }
        uint32_t y = mt[mti++];
        y ^= y >> 11; y ^= (y << 7) & 2636928640u; y ^= (y << 15) & 4022730752u; y ^= y >> 18;
        return y;
    };
    auto rdouble = [&]() -> double {
        uint32_t a = genrand() >> 5, b = genrand() >> 6;
        return (a * 67108864.0 + b) / 9007199254740992.0;
    };
    bool has_g = false; double gcache = 0.0;
    auto gauss = [&]() -> double {
        if (has_g) { has_g = false; return gcache; }
        double x1, x2, r2;
        do {
            x1 = 2.0 * rdouble() - 1.0;
            x2 = 2.0 * rdouble() - 1.0;
            r2 = x1*x1 + x2*x2;
        } while (r2 >= 1.0 || r2 == 0.0);
        double f = sqrt(-2.0 * log(r2) / r2);
        gcache = f * x1; has_g = true;
        return f * x2;
    };
    for (int i = 0; i < 3436; i++) out[i] = (float)(gauss() * 0.2);
}

static CGBuf h_cg;

// Persistent streams + events for graph-captured fork/join.
static cudaStream_t g_s2 = nullptr, g_s3 = nullptr;
static cudaEvent_t  g_evA = nullptr, g_evB = nullptr, g_evJoin = nullptr, g_evW = nullptr;

extern "C" void kernel_launch(void* const* d_in, const int* in_sizes, int n_in,
                              void* d_out, int out_size) {
    const float* sh      = (const float*)d_in[0];
    const float* rb      = (const float*)d_in[1];
    const float* tab     = (const float*)d_in[2];
    const float* wE      = (const float*)d_in[3];
    const float* bE      = (const float*)d_in[4];
    const int*   spec    = (const int*)d_in[5];
    const int*   centers = (const int*)d_in[6];
    const int*   nbrs    = (const int*)d_in[7];
    int N = in_sizes[5];
    int P = in_sizes[6];
    float* out = (float*)d_out;

    if (g_s2 == nullptr) {
        cudaStreamCreateWithFlags(&g_s2, cudaStreamNonBlocking);
        cudaStreamCreateWithFlags(&g_s3, cudaStreamNonBlocking);
        cudaEventCreateWithFlags(&g_evA, cudaEventDisableTiming);
        cudaEventCreateWithFlags(&g_evB, cudaEventDisableTiming);
        cudaEventCreateWithFlags(&g_evJoin, cudaEventDisableTiming);
        cudaEventCreateWithFlags(&g_evW, cudaEventDisableTiming);
    }

    gen_cg(h_cg.v);

    // s0: CG tables, then fork W-chain (needs only g_cgw)
    k_initcg<<<1, 256>>>(h_cg);
    cudaEventRecord(g_evA, 0);
    cudaStreamWaitEvent(g_s3, g_evA, 0);
    k_Wb2<<<(P + 7)/8, 256, 0, g_s3>>>(sh, rb, P);
    cudaEventRecord(g_evW, g_s3);

    // s0: init (zeros counts/S, embeddings), then fork invariant chain
    k_misc1<<<(N*240 + 255)/256, 256>>>(tab, spec, N);
    cudaEventRecord(g_evB, 0);
    cudaStreamWaitEvent(g_s2, g_evB, 0);
    k_invA<<<(P*64 + 255)/256, 256, 0, g_s2>>>(sh, rb, centers, nbrs, spec, P);
    k_invB<<<N, 256, 0, g_s2>>>(tab, N);
    k_tpA<<<(N + 3)/4, 256, 0, g_s2>>>(N);
    cudaEventRecord(g_evJoin, g_s2);

    // s0: counting sort (no W dependency anymore)
    k_hist<<<(P + 255)/256, 256>>>(centers, P);
    k_scan<<<1, 1024>>>(N);
    k_scatter<<<(P + 255)/256, 256>>>(centers, nbrs, P);

    // join all, then message passing + energy
    cudaStreamWaitEvent(0, g_evJoin, 0);
    cudaStreamWaitEvent(0, g_evW, 0);
    k_eqmp3<<<592, 256>>>(N);
    k_tpE<<<(N + 3)/4, 256>>>(wE, bE, out, N);
}